// round 2
// baseline (speedup 1.0000x reference)
#include <cuda_runtime.h>
#include <cuda_bf16.h>

#define N        1024
#define ED       256
#define HD       128
#define TSP      64      // pair-tile size

// ---------------- scratch (no allocation allowed) ----------------
__device__ float g_context[HD];
__device__ float g_Wf[ED * 2 * HD];      // fused weights [256][256]: cols 0-127 q, 128-255 k
__device__ float g_biasf[2 * HD];        // fused biases
__device__ float g_qk[N * 2 * HD];       // [i][0..127]=qp, [i][128..255]=kp

// ---------------- kernel A: context = relu(emb @ Wc + bc) ----------------
__global__ void ctx_kernel(const float* __restrict__ emb,
                           const float* __restrict__ Wc,
                           const float* __restrict__ bc) {
    int h = threadIdx.x;            // 128 threads
    float s = bc[h];
    #pragma unroll 8
    for (int e = 0; e < ED; e++)
        s = fmaf(emb[e], Wc[e * HD + h], s);
    g_context[h] = fmaxf(s, 0.0f);
}

// ---------------- kernel A2: fused biases -------------------------------
// biasf[h]      = b1[h] + sum_k (bq[k]+ctx[k]) * W1[k][h]
// biasf[128+h]  =         sum_k (bk[k]+ctx[k]) * W1[128+k][h]
__global__ void bias_kernel(const float* __restrict__ bq,
                            const float* __restrict__ bk,
                            const float* __restrict__ b1,
                            const float* __restrict__ W1) {
    __shared__ float sq[HD], sk[HD];
    int t = threadIdx.x;            // 256 threads
    if (t < HD) sq[t] = bq[t] + g_context[t];
    else        sk[t - HD] = bk[t - HD] + g_context[t - HD];
    __syncthreads();
    if (t < HD) {
        float s = b1[t];
        #pragma unroll 4
        for (int k = 0; k < HD; k++)
            s = fmaf(sq[k], W1[k * HD + t], s);
        g_biasf[t] = s;
    } else {
        int h = t - HD;
        float s = 0.0f;
        #pragma unroll 4
        for (int k = 0; k < HD; k++)
            s = fmaf(sk[k], W1[(HD + k) * HD + h], s);
        g_biasf[t] = s;
    }
}

// ---------------- kernel B: fused weights Wf = [Wq@W1top | Wk@W1bot] ------
// grid 64 blocks, each handles 4 rows (e) of the output; 256 threads = col.
__global__ void __launch_bounds__(256)
wfuse_kernel(const float* __restrict__ Wq,
             const float* __restrict__ Wk,
             const float* __restrict__ W1) {
    __shared__ float aq[4][HD], ak[4][HD];
    int b = blockIdx.x, t = threadIdx.x;
    int r0 = b * 4;
    #pragma unroll
    for (int l = 0; l < 4; l++) {
        int idx = t + 256 * l;
        if (idx < 512) {
            int r = idx >> 7, k = idx & 127;
            aq[r][k] = Wq[(r0 + r) * HD + k];
        } else {
            int idx2 = idx - 512;
            int r = idx2 >> 7, k = idx2 & 127;
            ak[r][k] = Wk[(r0 + r) * HD + k];
        }
    }
    __syncthreads();
    float acc0 = 0.f, acc1 = 0.f, acc2 = 0.f, acc3 = 0.f;
    if (t < HD) {
        const float* w1b = W1 + t;
        #pragma unroll 4
        for (int k = 0; k < HD; k++) {
            float w = w1b[k * HD];
            acc0 = fmaf(aq[0][k], w, acc0);
            acc1 = fmaf(aq[1][k], w, acc1);
            acc2 = fmaf(aq[2][k], w, acc2);
            acc3 = fmaf(aq[3][k], w, acc3);
        }
    } else {
        const float* w1b = W1 + HD * HD + (t - HD);
        #pragma unroll 4
        for (int k = 0; k < HD; k++) {
            float w = w1b[k * HD];
            acc0 = fmaf(ak[0][k], w, acc0);
            acc1 = fmaf(ak[1][k], w, acc1);
            acc2 = fmaf(ak[2][k], w, acc2);
            acc3 = fmaf(ak[3][k], w, acc3);
        }
    }
    g_Wf[(r0 + 0) * 256 + t] = acc0;
    g_Wf[(r0 + 1) * 256 + t] = acc1;
    g_Wf[(r0 + 2) * 256 + t] = acc2;
    g_Wf[(r0 + 3) * 256 + t] = acc3;
}

// ---------------- kernel C: GEMM g_qk = prev @ Wf + biasf ------------------
// C[1024,256] = A[1024,256] @ B[256,256]; tile 64(M) x 32(N), KC=32, 256 thr
__global__ void __launch_bounds__(256)
gemm_kernel(const float* __restrict__ prev) {
    __shared__ float AsT[32][65];   // [k][m], padded (stride 65 words -> conflict-free scatter)
    __shared__ float Bs[32][32];    // [k][n]
    int bx = blockIdx.x;            // n-tile 0..7
    int by = blockIdx.y;            // m-tile 0..15
    int t = threadIdx.x;
    int i0 = by * 64, nb = bx * 32;
    int tn = t & 7, tm = t >> 3;    // tn 0..7 (n), tm 0..31 (m)

    float acc[2][4] = {{0.f,0.f,0.f,0.f},{0.f,0.f,0.f,0.f}};

    for (int kt = 0; kt < ED; kt += 32) {
        __syncthreads();
        // load A tile (64 rows x 32 k), transposed into AsT[k][m]
        #pragma unroll
        for (int l = 0; l < 2; l++) {
            int idx = t + 256 * l;
            int e4 = idx & 7, i = idx >> 3;        // warp: 8 e4 x 4 i -> coalesced 128B/row
            float4 v = *(const float4*)&prev[(i0 + i) * ED + kt + 4 * e4];
            AsT[4*e4+0][i] = v.x; AsT[4*e4+1][i] = v.y;
            AsT[4*e4+2][i] = v.z; AsT[4*e4+3][i] = v.w;
        }
        // load B tile (32 k x 32 n)
        {
            int c4 = t & 7, row = t >> 3;
            float4 v = *(const float4*)&g_Wf[(kt + row) * 256 + nb + 4 * c4];
            *(float4*)&Bs[row][4 * c4] = v;
        }
        __syncthreads();
        #pragma unroll 8
        for (int k = 0; k < 32; k++) {
            float a0 = AsT[k][2 * tm];
            float a1 = AsT[k][2 * tm + 1];
            float4 bv = *(const float4*)&Bs[k][4 * tn];
            acc[0][0] = fmaf(a0, bv.x, acc[0][0]);
            acc[0][1] = fmaf(a0, bv.y, acc[0][1]);
            acc[0][2] = fmaf(a0, bv.z, acc[0][2]);
            acc[0][3] = fmaf(a0, bv.w, acc[0][3]);
            acc[1][0] = fmaf(a1, bv.x, acc[1][0]);
            acc[1][1] = fmaf(a1, bv.y, acc[1][1]);
            acc[1][2] = fmaf(a1, bv.z, acc[1][2]);
            acc[1][3] = fmaf(a1, bv.w, acc[1][3]);
        }
    }
    float b0 = g_biasf[nb + 4 * tn + 0];
    float b1v = g_biasf[nb + 4 * tn + 1];
    float b2v = g_biasf[nb + 4 * tn + 2];
    float b3 = g_biasf[nb + 4 * tn + 3];
    #pragma unroll
    for (int r = 0; r < 2; r++) {
        float4 o = make_float4(acc[r][0] + b0, acc[r][1] + b1v,
                               acc[r][2] + b2v, acc[r][3] + b3);
        *(float4*)&g_qk[(i0 + 2 * tm + r) * 256 + nb + 4 * tn] = o;
    }
}

// ---------------- kernel D: pair scores ------------------------------------
// packed f32x2: add + 2x max + fma = 4 issue slots / 2 elements
#define PSTEP(ACC, QP, KP, WP)                                        \
    asm("{\n\t"                                                       \
        ".reg .b64 s; .reg .f32 lo, hi;\n\t"                          \
        "add.rn.f32x2 s, %1, %2;\n\t"                                 \
        "mov.b64 {lo, hi}, s;\n\t"                                    \
        "max.f32 lo, lo, 0f00000000;\n\t"                             \
        "max.f32 hi, hi, 0f00000000;\n\t"                             \
        "mov.b64 s, {lo, hi};\n\t"                                    \
        "fma.rn.f32x2 %0, s, %3, %0;\n\t"                             \
        "}" : "+l"(ACC) : "l"(QP), "l"(KP), "l"(WP))

__global__ void __launch_bounds__(256, 1)
pair_kernel(const float* __restrict__ W2,
            const float* __restrict__ b2,
            float* __restrict__ out) {
    extern __shared__ float sm[];
    float* qs  = sm;                  // [64][128] swizzled
    float* ks  = sm + TSP * HD;       // [64][128] swizzled
    float* w2s = sm + 2 * TSP * HD;   // [128]

    // decode 1D block id -> upper-triangular tile (it <= jt), 16x16 tiles
    int rem = blockIdx.x;
    int it = 0;
    #pragma unroll
    for (int r = 0; r < 16; r++) {
        int len = 16 - r;
        if (rem < len) { it = r; break; }
        rem -= len;
    }
    int jt = it + rem;

    int t = threadIdx.x;
    int ibase = it * TSP, jbase = jt * TSP;

    // load tiles, XOR-swizzled: word(i, h4) = i*128 + 4*(h4 ^ ((i>>2)&7))
    #pragma unroll
    for (int l = 0; l < 8; l++) {
        int h4 = t & 31;
        int i = (t >> 5) + 8 * l;
        float4 qv = *(const float4*)&g_qk[(ibase + i) * 256 + 4 * h4];
        float4 kv = *(const float4*)&g_qk[(jbase + i) * 256 + HD + 4 * h4];
        int sw = 4 * (h4 ^ ((i >> 2) & 7));
        *(float4*)&qs[i * HD + sw] = qv;
        *(float4*)&ks[i * HD + sw] = kv;
    }
    if (t < HD) w2s[t] = W2[t];
    __syncthreads();

    int tx = t & 15, ty = t >> 4;
    int i0 = ty * 4, j0 = tx * 4;
    int swq = ty & 7, swk = tx & 7;

    unsigned long long acc[4][4];
    #pragma unroll
    for (int a = 0; a < 4; a++)
        #pragma unroll
        for (int b = 0; b < 4; b++)
            acc[a][b] = 0ull;

    #pragma unroll 2
    for (int h4 = 0; h4 < HD / 4; h4++) {
        int hq = 4 * (h4 ^ swq);
        int hk = 4 * (h4 ^ swk);
        ulonglong2 q[4], k[4];
        #pragma unroll
        for (int a = 0; a < 4; a++)
            q[a] = *(const ulonglong2*)&qs[(i0 + a) * HD + hq];
        #pragma unroll
        for (int b = 0; b < 4; b++)
            k[b] = *(const ulonglong2*)&ks[(j0 + b) * HD + hk];
        ulonglong2 w = *(const ulonglong2*)&w2s[4 * h4];
        #pragma unroll
        for (int a = 0; a < 4; a++)
            #pragma unroll
            for (int b = 0; b < 4; b++) {
                PSTEP(acc[a][b], q[a].x, k[b].x, w.x);
                PSTEP(acc[a][b], q[a].y, k[b].y, w.y);
            }
    }

    float bias = b2[0];
    #pragma unroll
    for (int a = 0; a < 4; a++) {
        int i = ibase + i0 + a;
        // row-major triu offset: i*N - i*(i+1)/2 + (j - i - 1)
        int rowoff = i * N - ((i * (i + 1)) >> 1) - i - 1;
        #pragma unroll
        for (int b = 0; b < 4; b++) {
            int j = jbase + j0 + b;
            if (i < j) {
                unsigned long long v = acc[a][b];
                float lo = __int_as_float((unsigned)v);
                float hi = __int_as_float((unsigned)(v >> 32));
                out[rowoff + j] = lo + hi + bias;
            }
        }
    }
}

// ---------------- launch ----------------
extern "C" void kernel_launch(void* const* d_in, const int* in_sizes, int n_in,
                              void* d_out, int out_size) {
    const float* emb  = (const float*)d_in[0];
    const float* prev = (const float*)d_in[1];
    const float* Wq   = (const float*)d_in[2];
    const float* bq   = (const float*)d_in[3];
    const float* Wk   = (const float*)d_in[4];
    const float* bk   = (const float*)d_in[5];
    const float* Wc   = (const float*)d_in[6];
    const float* bc   = (const float*)d_in[7];
    const float* W1   = (const float*)d_in[8];
    const float* b1   = (const float*)d_in[9];
    const float* W2   = (const float*)d_in[10];
    const float* b2   = (const float*)d_in[11];
    float* out = (float*)d_out;

    int pair_smem = (2 * TSP * HD + HD) * (int)sizeof(float);  // 66048
    cudaFuncSetAttribute(pair_kernel,
                         cudaFuncAttributeMaxDynamicSharedMemorySize, pair_smem);

    ctx_kernel<<<1, HD>>>(emb, Wc, bc);
    bias_kernel<<<1, 256>>>(bq, bk, b1, W1);
    wfuse_kernel<<<64, 256>>>(Wq, Wk, W1);
    gemm_kernel<<<dim3(8, 16), 256>>>(prev);
    pair_kernel<<<136, 256, pair_smem>>>(W2, b2, out);
}

// round 4
// speedup vs baseline: 1.5000x; 1.5000x over previous
#include <cuda_runtime.h>
#include <cuda_bf16.h>

#define N        1024
#define ED       256
#define HD       128
#define TSP      64      // pair-tile size

// ---------------- scratch (no allocation allowed) ----------------
__device__ float g_WfA[ED * 2 * HD];     // fused-weight partial, k 0..63
__device__ float g_WfB[ED * 2 * HD];     // fused-weight partial, k 64..127
__device__ float g_biasf[2 * HD];        // fused biases (q half includes b1)
__device__ float g_qkA[N * 2 * HD];      // qk partial, e 0..127
__device__ float g_qkB[N * 2 * HD];      // qk partial, e 128..255

// ---------------- kernel A: context + fused biases (one block) ------------
// ctx = relu(emb@Wc + bc)
// biasf[h]     = b1[h] + sum_k (bq[k]+ctx[k]) * W1[k][h]
// biasf[128+h] =         sum_k (bk[k]+ctx[k]) * W1[128+k][h]
__global__ void __launch_bounds__(256)
ctxbias_kernel(const float* __restrict__ emb,
               const float* __restrict__ Wc,
               const float* __restrict__ bc,
               const float* __restrict__ bq,
               const float* __restrict__ bk,
               const float* __restrict__ b1,
               const float* __restrict__ W1) {
    __shared__ float semb[ED];
    __shared__ float part[256];
    __shared__ float sq[HD], sk[HD];
    int t = threadIdx.x;
    semb[t] = emb[t];
    __syncthreads();
    {   // split the 256-deep ctx dot across two thread halves
        int half = t >> 7, h = t & 127;
        float s = 0.f;
        #pragma unroll 8
        for (int k = 0; k < 128; k++)
            s = fmaf(semb[half * 128 + k], Wc[(half * 128 + k) * HD + h], s);
        part[t] = s;
    }
    __syncthreads();
    if (t < HD) {
        float ctx = fmaxf(part[t] + part[t + 128] + bc[t], 0.f);
        sq[t] = bq[t] + ctx;
        sk[t] = bk[t] + ctx;
    }
    __syncthreads();
    if (t < HD) {
        float s = b1[t];
        #pragma unroll 8
        for (int k = 0; k < HD; k++)
            s = fmaf(sq[k], W1[k * HD + t], s);
        g_biasf[t] = s;
    } else {
        int h = t - HD;
        float s = 0.f;
        #pragma unroll 8
        for (int k = 0; k < HD; k++)
            s = fmaf(sk[k], W1[(HD + k) * HD + h], s);
        g_biasf[t] = s;
    }
}

// ---------------- kernel B: fused weights Wf = [Wq@W1top | Wk@W1bot] ------
// GEMM 256x256x128, split-K=2. grid (8 n, 4 m, 2 k), 128 threads, 4x4/thread.
__global__ void __launch_bounds__(128)
wfuse_kernel(const float* __restrict__ Wq,
             const float* __restrict__ Wk,
             const float* __restrict__ W1) {
    __shared__ float AsT[64 * 65];   // [k][e], scalar-store transpose, stride 65
    __shared__ float Bs[64][32];     // [k][n]
    int nb = blockIdx.x * 32;
    int e0 = blockIdx.y * 64;
    int k0 = blockIdx.z * 64;
    int half = nb >> 7;              // 0 -> q-cols (Wq/W1top), 1 -> k-cols (Wk/W1bot)
    int ncol = nb & 127;
    const float* A = half ? Wk : Wq;
    int t = threadIdx.x, tx = t & 7, ty = t >> 3;

    #pragma unroll
    for (int l = 0; l < 8; l++) {              // A: 64(e) x 64(k), transposed
        int idx = l * 128 + t;
        int e16 = idx & 15, i = idx >> 4;      // e16: k float4-group, i: e-row
        float4 v = *(const float4*)&A[(e0 + i) * HD + k0 + 4 * e16];
        AsT[(4 * e16 + 0) * 65 + i] = v.x;
        AsT[(4 * e16 + 1) * 65 + i] = v.y;
        AsT[(4 * e16 + 2) * 65 + i] = v.z;
        AsT[(4 * e16 + 3) * 65 + i] = v.w;
    }
    #pragma unroll
    for (int l = 0; l < 4; l++) {              // B: 64x32 floats, coalesced rows
        int idx = l * 128 + t;
        int c4 = idx & 7, row = idx >> 3;
        *(float4*)&Bs[row][4 * c4] =
            *(const float4*)&W1[(half * HD + k0 + row) * HD + ncol + 4 * c4];
    }
    __syncthreads();

    float acc[4][4] = {};
    #pragma unroll 4
    for (int k = 0; k < 64; k++) {
        float a0 = AsT[k * 65 + 4 * ty + 0];
        float a1 = AsT[k * 65 + 4 * ty + 1];
        float a2 = AsT[k * 65 + 4 * ty + 2];
        float a3 = AsT[k * 65 + 4 * ty + 3];
        float4 b = *(const float4*)&Bs[k][4 * tx];
        acc[0][0] = fmaf(a0, b.x, acc[0][0]); acc[0][1] = fmaf(a0, b.y, acc[0][1]);
        acc[0][2] = fmaf(a0, b.z, acc[0][2]); acc[0][3] = fmaf(a0, b.w, acc[0][3]);
        acc[1][0] = fmaf(a1, b.x, acc[1][0]); acc[1][1] = fmaf(a1, b.y, acc[1][1]);
        acc[1][2] = fmaf(a1, b.z, acc[1][2]); acc[1][3] = fmaf(a1, b.w, acc[1][3]);
        acc[2][0] = fmaf(a2, b.x, acc[2][0]); acc[2][1] = fmaf(a2, b.y, acc[2][1]);
        acc[2][2] = fmaf(a2, b.z, acc[2][2]); acc[2][3] = fmaf(a2, b.w, acc[2][3]);
        acc[3][0] = fmaf(a3, b.x, acc[3][0]); acc[3][1] = fmaf(a3, b.y, acc[3][1]);
        acc[3][2] = fmaf(a3, b.z, acc[3][2]); acc[3][3] = fmaf(a3, b.w, acc[3][3]);
    }
    float* outp = blockIdx.z ? g_WfB : g_WfA;
    #pragma unroll
    for (int r = 0; r < 4; r++)
        *(float4*)&outp[(e0 + 4 * ty + r) * 256 + nb + 4 * tx] =
            make_float4(acc[r][0], acc[r][1], acc[r][2], acc[r][3]);
}

// ---------------- kernel C: GEMM qk = prev @ Wf (split-K=2) ----------------
// grid (8 n, 16 m, 2 k), 128 threads, 64x32 tile, 4x4/thread, one sync.
__global__ void __launch_bounds__(128)
gemm_kernel(const float* __restrict__ prev) {
    extern __shared__ float sm[];
    float* AsT = sm;                 // [128(k)][65(m)] scalar-store transpose
    float* Bs  = sm + 128 * 65;      // [128][32]
    int nb = blockIdx.x * 32;
    int i0 = blockIdx.y * 64;
    int k0 = blockIdx.z * 128;
    int t = threadIdx.x, tx = t & 7, ty = t >> 3;

    #pragma unroll
    for (int l = 0; l < 16; l++) {             // A: 64(m) x 128(k), transposed
        int idx = l * 128 + t;
        int e4 = idx & 31, i = idx >> 5;       // e4: k float4-group, i: m-row
        float4 v = *(const float4*)&prev[(i0 + i) * ED + k0 + 4 * e4];
        AsT[(4 * e4 + 0) * 65 + i] = v.x;
        AsT[(4 * e4 + 1) * 65 + i] = v.y;
        AsT[(4 * e4 + 2) * 65 + i] = v.z;
        AsT[(4 * e4 + 3) * 65 + i] = v.w;
    }
    #pragma unroll
    for (int l = 0; l < 8; l++) {              // B: 128x32, sum wfuse partials
        int idx = l * 128 + t;
        int c4 = idx & 7, row = idx >> 3;
        int off = (k0 + row) * 256 + nb + 4 * c4;
        float4 a = *(const float4*)&g_WfA[off];
        float4 b = *(const float4*)&g_WfB[off];
        *(float4*)&Bs[row * 32 + 4 * c4] =
            make_float4(a.x + b.x, a.y + b.y, a.z + b.z, a.w + b.w);
    }
    __syncthreads();

    float acc[4][4] = {};
    #pragma unroll 4
    for (int k = 0; k < 128; k++) {
        float a0 = AsT[k * 65 + 4 * ty + 0];
        float a1 = AsT[k * 65 + 4 * ty + 1];
        float a2 = AsT[k * 65 + 4 * ty + 2];
        float a3 = AsT[k * 65 + 4 * ty + 3];
        float4 b = *(const float4*)&Bs[k * 32 + 4 * tx];
        acc[0][0] = fmaf(a0, b.x, acc[0][0]); acc[0][1] = fmaf(a0, b.y, acc[0][1]);
        acc[0][2] = fmaf(a0, b.z, acc[0][2]); acc[0][3] = fmaf(a0, b.w, acc[0][3]);
        acc[1][0] = fmaf(a1, b.x, acc[1][0]); acc[1][1] = fmaf(a1, b.y, acc[1][1]);
        acc[1][2] = fmaf(a1, b.z, acc[1][2]); acc[1][3] = fmaf(a1, b.w, acc[1][3]);
        acc[2][0] = fmaf(a2, b.x, acc[2][0]); acc[2][1] = fmaf(a2, b.y, acc[2][1]);
        acc[2][2] = fmaf(a2, b.z, acc[2][2]); acc[2][3] = fmaf(a2, b.w, acc[2][3]);
        acc[3][0] = fmaf(a3, b.x, acc[3][0]); acc[3][1] = fmaf(a3, b.y, acc[3][1]);
        acc[3][2] = fmaf(a3, b.z, acc[3][2]); acc[3][3] = fmaf(a3, b.w, acc[3][3]);
    }
    float* outp = blockIdx.z ? g_qkB : g_qkA;
    #pragma unroll
    for (int r = 0; r < 4; r++)
        *(float4*)&outp[(i0 + 4 * ty + r) * 256 + nb + 4 * tx] =
            make_float4(acc[r][0], acc[r][1], acc[r][2], acc[r][3]);
}

// ---------------- kernel D: pair scores ------------------------------------
#define PSTEP(ACC, QP, KP, WP)                                        \
    asm("{\n\t"                                                       \
        ".reg .b64 s; .reg .f32 lo, hi;\n\t"                          \
        "add.rn.f32x2 s, %1, %2;\n\t"                                 \
        "mov.b64 {lo, hi}, s;\n\t"                                    \
        "max.f32 lo, lo, 0f00000000;\n\t"                             \
        "max.f32 hi, hi, 0f00000000;\n\t"                             \
        "mov.b64 s, {lo, hi};\n\t"                                    \
        "fma.rn.f32x2 %0, s, %3, %0;\n\t"                             \
        "}" : "+l"(ACC) : "l"(QP), "l"(KP), "l"(WP))

__global__ void __launch_bounds__(256, 1)
pair_kernel(const float* __restrict__ W2,
            const float* __restrict__ b2,
            float* __restrict__ out) {
    extern __shared__ float sm[];
    float* qs  = sm;                  // [64][128] swizzled, bias folded
    float* ks  = sm + TSP * HD;       // [64][128] swizzled, bias folded
    float* w2s = sm + 2 * TSP * HD;   // [128]

    // decode 1D block id -> upper-triangular tile (it <= jt), 16x16 tiles
    int rem = blockIdx.x;
    int it = 0;
    #pragma unroll
    for (int r = 0; r < 16; r++) {
        int len = 16 - r;
        if (rem < len) { it = r; break; }
        rem -= len;
    }
    int jt = it + rem;

    int t = threadIdx.x;
    int ibase = it * TSP, jbase = jt * TSP;

    // load tiles: sum split-K partials + fold fused bias; XOR-swizzled rows
    {
        int h4 = t & 31;                       // fixed column group per thread
        float4 bq4 = *(const float4*)&g_biasf[4 * h4];
        float4 bk4 = *(const float4*)&g_biasf[HD + 4 * h4];
        #pragma unroll
        for (int l = 0; l < 8; l++) {
            int i = (t >> 5) + 8 * l;
            int qo = (ibase + i) * 256 + 4 * h4;
            int ko = (jbase + i) * 256 + HD + 4 * h4;
            float4 qa = *(const float4*)&g_qkA[qo];
            float4 qb = *(const float4*)&g_qkB[qo];
            float4 ka = *(const float4*)&g_qkA[ko];
            float4 kb = *(const float4*)&g_qkB[ko];
            float4 qv = make_float4(qa.x + qb.x + bq4.x, qa.y + qb.y + bq4.y,
                                    qa.z + qb.z + bq4.z, qa.w + qb.w + bq4.w);
            float4 kv = make_float4(ka.x + kb.x + bk4.x, ka.y + kb.y + bk4.y,
                                    ka.z + kb.z + bk4.z, ka.w + kb.w + bk4.w);
            int sw = 4 * (h4 ^ ((i >> 2) & 7));
            *(float4*)&qs[i * HD + sw] = qv;
            *(float4*)&ks[i * HD + sw] = kv;
        }
    }
    if (t < HD) w2s[t] = W2[t];
    __syncthreads();

    int tx = t & 15, ty = t >> 4;
    int i0 = ty * 4, j0 = tx * 4;
    int swq = ty & 7, swk = tx & 7;

    unsigned long long acc[4][4];
    #pragma unroll
    for (int a = 0; a < 4; a++)
        #pragma unroll
        for (int b = 0; b < 4; b++)
            acc[a][b] = 0ull;

    #pragma unroll 2
    for (int h4 = 0; h4 < HD / 4; h4++) {
        int hq = 4 * (h4 ^ swq);
        int hk = 4 * (h4 ^ swk);
        ulonglong2 q[4], k[4];
        #pragma unroll
        for (int a = 0; a < 4; a++)
            q[a] = *(const ulonglong2*)&qs[(i0 + a) * HD + hq];
        #pragma unroll
        for (int b = 0; b < 4; b++)
            k[b] = *(const ulonglong2*)&ks[(j0 + b) * HD + hk];
        ulonglong2 w = *(const ulonglong2*)&w2s[4 * h4];
        #pragma unroll
        for (int a = 0; a < 4; a++)
            #pragma unroll
            for (int b = 0; b < 4; b++) {
                PSTEP(acc[a][b], q[a].x, k[b].x, w.x);
                PSTEP(acc[a][b], q[a].y, k[b].y, w.y);
            }
    }

    float bias = b2[0];
    #pragma unroll
    for (int a = 0; a < 4; a++) {
        int i = ibase + i0 + a;
        int rowoff = i * N - ((i * (i + 1)) >> 1) - i - 1;
        #pragma unroll
        for (int b = 0; b < 4; b++) {
            int j = jbase + j0 + b;
            if (i < j) {
                unsigned long long v = acc[a][b];
                float lo = __int_as_float((unsigned)v);
                float hi = __int_as_float((unsigned)(v >> 32));
                out[rowoff + j] = lo + hi + bias;
            }
        }
    }
}

// ---------------- launch ----------------
extern "C" void kernel_launch(void* const* d_in, const int* in_sizes, int n_in,
                              void* d_out, int out_size) {
    const float* emb  = (const float*)d_in[0];
    const float* prev = (const float*)d_in[1];
    const float* Wq   = (const float*)d_in[2];
    const float* bq   = (const float*)d_in[3];
    const float* Wk   = (const float*)d_in[4];
    const float* bk   = (const float*)d_in[5];
    const float* Wc   = (const float*)d_in[6];
    const float* bc   = (const float*)d_in[7];
    const float* W1   = (const float*)d_in[8];
    const float* b1   = (const float*)d_in[9];
    const float* W2   = (const float*)d_in[10];
    const float* b2   = (const float*)d_in[11];
    float* out = (float*)d_out;

    int gemm_smem = (128 * 65 + 128 * 32) * (int)sizeof(float);      // 49664
    int pair_smem = (2 * TSP * HD + HD) * (int)sizeof(float);        // 66048
    cudaFuncSetAttribute(gemm_kernel,
                         cudaFuncAttributeMaxDynamicSharedMemorySize, gemm_smem);
    cudaFuncSetAttribute(pair_kernel,
                         cudaFuncAttributeMaxDynamicSharedMemorySize, pair_smem);

    ctxbias_kernel<<<1, 256>>>(emb, Wc, bc, bq, bk, b1, W1);
    wfuse_kernel<<<dim3(8, 4, 2), 128>>>(Wq, Wk, W1);
    gemm_kernel<<<dim3(8, 16, 2), 128, gemm_smem>>>(prev);
    pair_kernel<<<136, 256, pair_smem>>>(W2, b2, out);
}